// round 9
// baseline (speedup 1.0000x reference)
#include <cuda_runtime.h>
#include <math.h>

// Problem shape: B=2, S=4096, H=1024, M=B*S=8192
#define BDIM 2
#define SDIM 4096
#define HDIM 1024
#define MDIM 8192

#define BM 128
#define BN 128
#define BK 8
#define PAD 132   // floats per smem k-row (128 payload + 4 pad)

// Scratch
__device__ float g_q[(size_t)MDIM * HDIM];
__device__ float g_k[(size_t)MDIM * HDIM];
__device__ float g_v[(size_t)MDIM * HDIM];
__device__ float g_attn[(size_t)MDIM * HDIM];
__device__ float g_s[(size_t)BDIM * SDIM * SDIM];

// ---------------------------------------------------------------------------
// Fragment helpers. Thread tile 4(m) x 8(n); warp tile 32x32 (8x4 lanes);
// CTA 128x128 via 4x4 warps, 512 threads.
// ---------------------------------------------------------------------------
__device__ __forceinline__ void load_fa(float* fa, const float* as, int am) {
    float4 v = *reinterpret_cast<const float4*>(as + am);
    fa[0] = v.x; fa[1] = v.y; fa[2] = v.z; fa[3] = v.w;
}
__device__ __forceinline__ void load_fb(float* fb, const float* bs, int bn) {
    float4 v0 = *reinterpret_cast<const float4*>(bs + bn);
    float4 v1 = *reinterpret_cast<const float4*>(bs + bn + 16);
    fb[0] = v0.x; fb[1] = v0.y; fb[2] = v0.z; fb[3] = v0.w;
    fb[4] = v1.x; fb[5] = v1.y; fb[6] = v1.z; fb[7] = v1.w;
}

__device__ __forceinline__ void epilogue_store(
    float acc[4][8], float* __restrict__ C, long long ldC,
    long long m0, long long n0, int am, int bn,
    const float* __restrict__ bias, float alpha)
{
    float bb[8];
    if (bias) {
        float4 b0 = *reinterpret_cast<const float4*>(bias + n0 + bn);
        float4 b1 = *reinterpret_cast<const float4*>(bias + n0 + bn + 16);
        bb[0]=b0.x; bb[1]=b0.y; bb[2]=b0.z; bb[3]=b0.w;
        bb[4]=b1.x; bb[5]=b1.y; bb[6]=b1.z; bb[7]=b1.w;
    } else {
        #pragma unroll
        for (int j = 0; j < 8; j++) bb[j] = 0.f;
    }
    #pragma unroll
    for (int i = 0; i < 4; i++) {
        long long row = m0 + am + i;
        float* Cr = C + row * ldC + n0 + bn;
        float4 o0, o1;
        o0.x = alpha * acc[i][0] + bb[0];
        o0.y = alpha * acc[i][1] + bb[1];
        o0.z = alpha * acc[i][2] + bb[2];
        o0.w = alpha * acc[i][3] + bb[3];
        o1.x = alpha * acc[i][4] + bb[4];
        o1.y = alpha * acc[i][5] + bb[5];
        o1.z = alpha * acc[i][6] + bb[6];
        o1.w = alpha * acc[i][7] + bb[7];
        *reinterpret_cast<float4*>(Cr)      = o0;
        *reinterpret_cast<float4*>(Cr + 16) = o1;
    }
}

// ---------------------------------------------------------------------------
// NT GEMM: C[m,n] = alpha * sum_k A[m,k]*B[n,k] + bias[n]
// A:[M,K], B:[N,K] row-major. M,N % 128 == 0, K % 8 == 0.
// 512 threads: tid<256 stage A (transposed), tid>=256 stage B (transposed).
// ---------------------------------------------------------------------------
__global__ __launch_bounds__(512, 1)
void sgemm_nt(const float* __restrict__ A, const float* __restrict__ B,
              const float* __restrict__ bias, float* __restrict__ C,
              int M, int N, int K, float alpha,
              long long sA, long long sB, long long sC)
{
    __shared__ float As[2][BK * PAD];
    __shared__ float Bs[2][BK * PAD];

    A += (long long)blockIdx.z * sA;
    B += (long long)blockIdx.z * sB;
    C += (long long)blockIdx.z * sC;

    const int tid  = threadIdx.x;
    const int lane = tid & 31;
    const int wid  = tid >> 5;
    const int am = (wid & 3) * 32 + (lane & 7) * 4;   // warp_m*32 + lane_m*4
    const int bn = (wid >> 2) * 32 + (lane >> 3) * 4; // warp_n*32 + lane_n*4

    const long long m0 = (long long)blockIdx.y * BM;
    const long long n0 = (long long)blockIdx.x * BN;

    // Loader role: 256 threads for A, 256 for B. Both are [rows][K] transposed
    // into [k][row] smem tiles via scalar stores (conflict-free: 132-stride).
    const int  ltid = tid & 255;
    const int  lrow = ltid >> 1;
    const int  lk   = (ltid & 1) * 4;
    const bool isA  = tid < 256;
    const float* Gp = isA ? (A + (m0 + lrow) * K + lk)
                          : (B + (n0 + lrow) * K + lk);

    const int nt = K / BK;

    float4 pre = *reinterpret_cast<const float4*>(Gp);
    {
        float* s0 = isA ? As[0] : Bs[0];
        s0[(lk + 0) * PAD + lrow] = pre.x;
        s0[(lk + 1) * PAD + lrow] = pre.y;
        s0[(lk + 2) * PAD + lrow] = pre.z;
        s0[(lk + 3) * PAD + lrow] = pre.w;
    }
    __syncthreads();

    float acc[4][8];
    #pragma unroll
    for (int i = 0; i < 4; i++)
        #pragma unroll
        for (int j = 0; j < 8; j++) acc[i][j] = 0.f;

    float fa[2][4], fb[2][8];
    load_fa(fa[0], As[0], am);
    load_fb(fb[0], Bs[0], bn);

    for (int t = 0; t < nt; ++t) {
        const int cur = t & 1;
        if (t + 1 < nt)
            pre = *reinterpret_cast<const float4*>(Gp + (long long)(t + 1) * BK);

        #pragma unroll
        for (int kk = 0; kk < BK; ++kk) {
            const int c = kk & 1;
            if (kk + 1 < BK) {
                load_fa(fa[c ^ 1], As[cur] + (kk + 1) * PAD, am);
                load_fb(fb[c ^ 1], Bs[cur] + (kk + 1) * PAD, bn);
            }
            #pragma unroll
            for (int i = 0; i < 4; i++)
                #pragma unroll
                for (int j = 0; j < 8; j++)
                    acc[i][j] += fa[c][i] * fb[c][j];
        }

        if (t + 1 < nt) {
            float* sd = isA ? As[cur ^ 1] : Bs[cur ^ 1];
            sd[(lk + 0) * PAD + lrow] = pre.x;
            sd[(lk + 1) * PAD + lrow] = pre.y;
            sd[(lk + 2) * PAD + lrow] = pre.z;
            sd[(lk + 3) * PAD + lrow] = pre.w;
        }
        __syncthreads();
        if (t + 1 < nt) {
            load_fa(fa[0], As[cur ^ 1], am);
            load_fb(fb[0], Bs[cur ^ 1], bn);
        }
    }

    epilogue_store(acc, C, N, m0, n0, am, bn, bias, alpha);
}

// ---------------------------------------------------------------------------
// NN GEMM: C[m,n] = sum_k A[m,k]*B[k,n]   (A:[M,K], B:[K,N], row-major)
// Threads 0-255 stage A (transposed); 256-511 stage B (direct rows).
// ---------------------------------------------------------------------------
__global__ __launch_bounds__(512, 1)
void sgemm_nn(const float* __restrict__ A, const float* __restrict__ B,
              float* __restrict__ C,
              int M, int N, int K,
              long long sA, long long sB, long long sC)
{
    __shared__ float As[2][BK * PAD];
    __shared__ float Bs[2][BK * PAD];

    A += (long long)blockIdx.z * sA;
    B += (long long)blockIdx.z * sB;
    C += (long long)blockIdx.z * sC;

    const int tid  = threadIdx.x;
    const int lane = tid & 31;
    const int wid  = tid >> 5;
    const int am = (wid & 3) * 32 + (lane & 7) * 4;
    const int bn = (wid >> 2) * 32 + (lane >> 3) * 4;

    const long long m0 = (long long)blockIdx.y * BM;
    const long long n0 = (long long)blockIdx.x * BN;

    const int  ltid = tid & 255;
    const bool isA  = tid < 256;
    // A loader: 128 rows x 8k, one float4 per thread (transpose on store)
    const int  lrow = ltid >> 1;
    const int  lk   = (ltid & 1) * 4;
    // B loader: 8 rows x 128 cols, one float4 per thread (direct store)
    const int  brow = ltid >> 5;          // 0..7
    const int  bcol = (ltid & 31) * 4;    // 0..124

    const float* Gp = isA ? (A + (m0 + lrow) * K + lk)
                          : (B + (long long)brow * N + n0 + bcol);
    const long long gstep = isA ? (long long)BK : (long long)BK * N;

    const int nt = K / BK;

    float4 pre = *reinterpret_cast<const float4*>(Gp);
    if (isA) {
        As[0][(lk + 0) * PAD + lrow] = pre.x;
        As[0][(lk + 1) * PAD + lrow] = pre.y;
        As[0][(lk + 2) * PAD + lrow] = pre.z;
        As[0][(lk + 3) * PAD + lrow] = pre.w;
    } else {
        *reinterpret_cast<float4*>(&Bs[0][brow * PAD + bcol]) = pre;
    }
    __syncthreads();

    float acc[4][8];
    #pragma unroll
    for (int i = 0; i < 4; i++)
        #pragma unroll
        for (int j = 0; j < 8; j++) acc[i][j] = 0.f;

    float fa[2][4], fb[2][8];
    load_fa(fa[0], As[0], am);
    load_fb(fb[0], Bs[0], bn);

    for (int t = 0; t < nt; ++t) {
        const int cur = t & 1;
        if (t + 1 < nt)
            pre = *reinterpret_cast<const float4*>(Gp + (long long)(t + 1) * gstep);

        #pragma unroll
        for (int kk = 0; kk < BK; ++kk) {
            const int c = kk & 1;
            if (kk + 1 < BK) {
                load_fa(fa[c ^ 1], As[cur] + (kk + 1) * PAD, am);
                load_fb(fb[c ^ 1], Bs[cur] + (kk + 1) * PAD, bn);
            }
            #pragma unroll
            for (int i = 0; i < 4; i++)
                #pragma unroll
                for (int j = 0; j < 8; j++)
                    acc[i][j] += fa[c][i] * fb[c][j];
        }

        if (t + 1 < nt) {
            if (isA) {
                float* sd = As[cur ^ 1];
                sd[(lk + 0) * PAD + lrow] = pre.x;
                sd[(lk + 1) * PAD + lrow] = pre.y;
                sd[(lk + 2) * PAD + lrow] = pre.z;
                sd[(lk + 3) * PAD + lrow] = pre.w;
            } else {
                *reinterpret_cast<float4*>(&Bs[cur ^ 1][brow * PAD + bcol]) = pre;
            }
        }
        __syncthreads();
        if (t + 1 < nt) {
            load_fa(fa[0], As[cur ^ 1], am);
            load_fb(fb[0], Bs[cur ^ 1], bn);
        }
    }

    epilogue_store(acc, C, N, m0, n0, am, bn, nullptr, 1.f);
}

// ---------------------------------------------------------------------------
// Row softmax over 4096 columns, one block (256 threads) per row, in place.
// ---------------------------------------------------------------------------
__device__ __forceinline__ float warp_max(float v) {
    #pragma unroll
    for (int o = 16; o > 0; o >>= 1) v = fmaxf(v, __shfl_xor_sync(0xffffffffu, v, o));
    return v;
}
__device__ __forceinline__ float warp_sum(float v) {
    #pragma unroll
    for (int o = 16; o > 0; o >>= 1) v += __shfl_xor_sync(0xffffffffu, v, o);
    return v;
}

__global__ __launch_bounds__(256)
void softmax_rows(float* __restrict__ S)
{
    const int tid = threadIdx.x;
    float* r = S + (size_t)blockIdx.x * SDIM;

    __shared__ float red[8];

    float v[16];
    float mx = -1e30f;
    #pragma unroll
    for (int i = 0; i < 16; i++) {
        v[i] = r[tid + i * 256];
        mx = fmaxf(mx, v[i]);
    }
    mx = warp_max(mx);
    if ((tid & 31) == 0) red[tid >> 5] = mx;
    __syncthreads();
    {
        float t = (tid < 8) ? red[tid] : -1e30f;
        t = warp_max(t);
        if (tid == 0) red[0] = t;
    }
    __syncthreads();
    mx = red[0];
    __syncthreads();

    float sum = 0.f;
    #pragma unroll
    for (int i = 0; i < 16; i++) {
        v[i] = __expf(v[i] - mx);
        sum += v[i];
    }
    sum = warp_sum(sum);
    if ((tid & 31) == 0) red[tid >> 5] = sum;
    __syncthreads();
    {
        float t = (tid < 8) ? red[tid] : 0.f;
        t = warp_sum(t);
        if (tid == 0) red[0] = t;
    }
    __syncthreads();
    const float inv = 1.f / red[0];

    #pragma unroll
    for (int i = 0; i < 16; i++)
        r[tid + i * 256] = v[i] * inv;
}

// ---------------------------------------------------------------------------
// Launch
// ---------------------------------------------------------------------------
extern "C" void kernel_launch(void* const* d_in, const int* in_sizes, int n_in,
                              void* d_out, int out_size)
{
    const float* x  = (const float*)d_in[0];
    const float* Wq = (const float*)d_in[1];
    const float* bq = (const float*)d_in[2];
    const float* Wk = (const float*)d_in[3];
    const float* bk = (const float*)d_in[4];
    const float* Wv = (const float*)d_in[5];
    const float* bv = (const float*)d_in[6];
    const float* Wo = (const float*)d_in[7];
    const float* bo = (const float*)d_in[8];
    float* out = (float*)d_out;

    const dim3 blk(512);

    // QKV projections: [8192,1024] = x[8192,1024] @ W^T + b
    dim3 gproj(HDIM / BN, MDIM / BM, 1);   // (8, 64)
    sgemm_nt<<<gproj, blk>>>(x, Wq, bq, g_q, MDIM, HDIM, HDIM, 1.f, 0, 0, 0);
    sgemm_nt<<<gproj, blk>>>(x, Wk, bk, g_k, MDIM, HDIM, HDIM, 1.f, 0, 0, 0);
    sgemm_nt<<<gproj, blk>>>(x, Wv, bv, g_v, MDIM, HDIM, HDIM, 1.f, 0, 0, 0);

    // scores = Q K^T / 8  (per batch)
    dim3 gsc(SDIM / BN, SDIM / BM, BDIM);  // (32, 32, 2)
    sgemm_nt<<<gsc, blk>>>(g_q, g_k, nullptr, g_s, SDIM, SDIM, HDIM, 0.125f,
                           (long long)SDIM * HDIM, (long long)SDIM * HDIM,
                           (long long)SDIM * SDIM);

    // softmax over rows (8192 rows of 4096), in place
    softmax_rows<<<BDIM * SDIM, 256>>>(g_s);

    // attn = P V  (per batch)
    dim3 gpv(HDIM / BN, SDIM / BM, BDIM);  // (8, 32, 2)
    sgemm_nn<<<gpv, blk>>>(g_s, g_v, g_attn, SDIM, HDIM, SDIM,
                           (long long)SDIM * SDIM, (long long)SDIM * HDIM,
                           (long long)SDIM * HDIM);

    // out = attn Wo^T + bo
    sgemm_nt<<<gproj, blk>>>(g_attn, Wo, bo, out, MDIM, HDIM, HDIM, 1.f, 0, 0, 0);
}

// round 10
// speedup vs baseline: 1.3521x; 1.3521x over previous
#include <cuda_runtime.h>
#include <math.h>

// Problem shape: B=2, S=4096, H=1024, M=B*S=8192
#define BDIM 2
#define SDIM 4096
#define HDIM 1024
#define MDIM 8192

#define BM 128
#define BN 128
#define BK 16
#define APAD 132                 // floats per As k-row
#define BPAD 264                 // floats per Bs2 k-row (duplicated pairs)
#define AS_F (BK * APAD)
#define BS_F (BK * BPAD)
#define STG_F (AS_F + BS_F)
#define DSMEM_BYTES (2 * STG_F * 4)  // 50688 bytes

// Scratch
__device__ float g_wqt[(size_t)HDIM * HDIM];   // Wq^T
__device__ float g_G[(size_t)HDIM * HDIM];     // Wq^T * Wk
__device__ float g_H[(size_t)HDIM * HDIM];     // Wo * Wv
__device__ float g_T[(size_t)MDIM * HDIM];     // X * G
__device__ float g_U[(size_t)MDIM * HDIM];     // P * X
__device__ float g_s[(size_t)BDIM * SDIM * SDIM];
__device__ float g_c[MDIM];                    // 0.125 * X * (Wk^T bq)
__device__ float g_u[HDIM];                    // Wk^T bq
__device__ float g_d[HDIM];                    // Wo bv + bo

typedef unsigned long long u64;

__device__ __forceinline__ void ffma2(u64& d, u64 a, u64 b) {
    asm("fma.rn.f32x2 %0, %1, %2, %0;" : "+l"(d) : "l"(a), "l"(b));
}
__device__ __forceinline__ float2 unpack2(u64 v) {
    float2 f;
    asm("mov.b64 {%0, %1}, %2;" : "=f"(f.x), "=f"(f.y) : "l"(v));
    return f;
}

// ---------------------------------------------------------------------------
// Inner machinery (R8): As[k][m] transposed, Bs2[k][2n] duplicated pairs.
// Thread computes 8(m) x 8(n) as 4x8 f32x2 (m-pairs).
// ---------------------------------------------------------------------------
__device__ __forceinline__ void compute_stage(
    const float* __restrict__ asb, const float* __restrict__ bsb,
    int ty, int tx, u64 acc[4][8])
{
    #pragma unroll
    for (int kk = 0; kk < BK; ++kk) {
        const float* ar = asb + kk * APAD;
        const float* br = bsb + kk * BPAD;
        ulonglong2 av0 = *reinterpret_cast<const ulonglong2*>(ar + ty * 4);
        ulonglong2 av1 = *reinterpret_cast<const ulonglong2*>(ar + 64 + ty * 4);
        ulonglong2 bv0 = *reinterpret_cast<const ulonglong2*>(br + 8 * tx);
        ulonglong2 bv1 = *reinterpret_cast<const ulonglong2*>(br + 8 * tx + 4);
        ulonglong2 bv2 = *reinterpret_cast<const ulonglong2*>(br + 128 + 8 * tx);
        ulonglong2 bv3 = *reinterpret_cast<const ulonglong2*>(br + 128 + 8 * tx + 4);
        u64 a_[4] = {av0.x, av0.y, av1.x, av1.y};
        u64 b_[8] = {bv0.x, bv0.y, bv1.x, bv1.y, bv2.x, bv2.y, bv3.x, bv3.y};
        #pragma unroll
        for (int mi = 0; mi < 4; mi++)
            #pragma unroll
            for (int j = 0; j < 8; j++)
                ffma2(acc[mi][j], a_[mi], b_[j]);
    }
}

__device__ __forceinline__ void epilogue_store(
    u64 acc[4][8], float* __restrict__ C, long long ldC,
    long long m0, long long n0, int ty, int tx,
    const float* __restrict__ bias, float alpha)
{
    float bb[8];
    #pragma unroll
    for (int jh = 0; jh < 2; jh++) {
        long long n = n0 + jh * 64 + tx * 4;
        if (bias) {
            float4 b = *reinterpret_cast<const float4*>(bias + n);
            bb[jh*4+0] = b.x; bb[jh*4+1] = b.y; bb[jh*4+2] = b.z; bb[jh*4+3] = b.w;
        } else {
            bb[jh*4+0] = bb[jh*4+1] = bb[jh*4+2] = bb[jh*4+3] = 0.f;
        }
    }
    #pragma unroll
    for (int mi = 0; mi < 4; mi++) {
        long long r0 = (mi < 2) ? (m0 + ty * 4 + 2 * mi)
                                : (m0 + 64 + ty * 4 + 2 * (mi - 2));
        float2 p[8];
        #pragma unroll
        for (int j = 0; j < 8; j++) p[j] = unpack2(acc[mi][j]);
        #pragma unroll
        for (int jh = 0; jh < 2; jh++) {
            long long n = n0 + jh * 64 + tx * 4;
            float4 lo, hi;
            lo.x = alpha * p[jh*4+0].x + bb[jh*4+0];
            lo.y = alpha * p[jh*4+1].x + bb[jh*4+1];
            lo.z = alpha * p[jh*4+2].x + bb[jh*4+2];
            lo.w = alpha * p[jh*4+3].x + bb[jh*4+3];
            hi.x = alpha * p[jh*4+0].y + bb[jh*4+0];
            hi.y = alpha * p[jh*4+1].y + bb[jh*4+1];
            hi.z = alpha * p[jh*4+2].y + bb[jh*4+2];
            hi.w = alpha * p[jh*4+3].y + bb[jh*4+3];
            *reinterpret_cast<float4*>(C + r0 * ldC + n)       = lo;
            *reinterpret_cast<float4*>(C + (r0 + 1) * ldC + n) = hi;
        }
    }
}

// ---------------------------------------------------------------------------
// NT GEMM: C[m,n] = alpha * sum_k A[m,k]*B[n,k] + bias[n]   (ld = K for A,B)
// bias has per-batch stride sBias.
// ---------------------------------------------------------------------------
__global__ __launch_bounds__(256, 2)
void sgemm_nt(const float* __restrict__ A, const float* __restrict__ B,
              const float* __restrict__ bias, float* __restrict__ C,
              int M, int N, int K, float alpha,
              long long sA, long long sB, long long sC, long long sBias)
{
    extern __shared__ float sm[];

    A += (long long)blockIdx.z * sA;
    B += (long long)blockIdx.z * sB;
    C += (long long)blockIdx.z * sC;
    if (bias) bias += (long long)blockIdx.z * sBias;

    const int tid = threadIdx.x;
    const int tx = tid & 15;
    const int ty = tid >> 4;

    const long long m0 = (long long)blockIdx.y * BM;
    const long long n0 = (long long)blockIdx.x * BN;

    const int lrow = tid >> 1;
    const int lk   = (tid & 1) * 4;

    const float* Ap = A + (m0 + lrow) * K + lk;
    const float* Bp = B + (n0 + lrow) * K + lk;

    const int nt = K / BK;

    float4 pa0, pa1, pb0, pb1;
    pa0 = *reinterpret_cast<const float4*>(Ap);
    pa1 = *reinterpret_cast<const float4*>(Ap + 8);
    pb0 = *reinterpret_cast<const float4*>(Bp);
    pb1 = *reinterpret_cast<const float4*>(Bp + 8);

    {
        float* as0 = sm;
        float* bs0 = sm + AS_F;
        #pragma unroll
        for (int i = 0; i < 4; i++) {
            as0[(lk + i) * APAD + lrow]     = (&pa0.x)[i];
            as0[(lk + 8 + i) * APAD + lrow] = (&pa1.x)[i];
            float v0 = (&pb0.x)[i], v1 = (&pb1.x)[i];
            *reinterpret_cast<float2*>(&bs0[(lk + i) * BPAD + 2 * lrow])     = make_float2(v0, v0);
            *reinterpret_cast<float2*>(&bs0[(lk + 8 + i) * BPAD + 2 * lrow]) = make_float2(v1, v1);
        }
    }
    __syncthreads();

    u64 acc[4][8];
    #pragma unroll
    for (int i = 0; i < 4; i++)
        #pragma unroll
        for (int j = 0; j < 8; j++) acc[i][j] = 0ULL;

    for (int t = 0; t < nt; ++t) {
        const int cur = t & 1;
        if (t + 1 < nt) {
            const long long off = (long long)(t + 1) * BK;
            pa0 = *reinterpret_cast<const float4*>(Ap + off);
            pa1 = *reinterpret_cast<const float4*>(Ap + off + 8);
            pb0 = *reinterpret_cast<const float4*>(Bp + off);
            pb1 = *reinterpret_cast<const float4*>(Bp + off + 8);
        }

        compute_stage(sm + cur * STG_F, sm + cur * STG_F + AS_F, ty, tx, acc);

        if (t + 1 < nt) {
            float* asn = sm + (cur ^ 1) * STG_F;
            float* bsn = asn + AS_F;
            #pragma unroll
            for (int i = 0; i < 4; i++) {
                asn[(lk + i) * APAD + lrow]     = (&pa0.x)[i];
                asn[(lk + 8 + i) * APAD + lrow] = (&pa1.x)[i];
                float v0 = (&pb0.x)[i], v1 = (&pb1.x)[i];
                *reinterpret_cast<float2*>(&bsn[(lk + i) * BPAD + 2 * lrow])     = make_float2(v0, v0);
                *reinterpret_cast<float2*>(&bsn[(lk + 8 + i) * BPAD + 2 * lrow]) = make_float2(v1, v1);
            }
        }
        __syncthreads();
    }

    epilogue_store(acc, C, N, m0, n0, ty, tx, bias, alpha);
}

// ---------------------------------------------------------------------------
// NN GEMM: C[m,n] = sum_k A[m,k]*B[k,n]   (ldA = K, ldB = N)
// ---------------------------------------------------------------------------
__global__ __launch_bounds__(256, 2)
void sgemm_nn(const float* __restrict__ A, const float* __restrict__ B,
              float* __restrict__ C,
              int M, int N, int K,
              long long sA, long long sB, long long sC)
{
    extern __shared__ float sm[];

    A += (long long)blockIdx.z * sA;
    B += (long long)blockIdx.z * sB;
    C += (long long)blockIdx.z * sC;

    const int tid = threadIdx.x;
    const int tx = tid & 15;
    const int ty = tid >> 4;

    const long long m0 = (long long)blockIdx.y * BM;
    const long long n0 = (long long)blockIdx.x * BN;

    const int lrow = tid >> 1;
    const int lk   = (tid & 1) * 4;
    const int brow = tid >> 4;           // 0..15
    const int bcol = (tid & 15) * 4;     // 0..60

    const float* Ap = A + (m0 + lrow) * K + lk;
    const float* Bp = B + (long long)brow * N + n0 + bcol;

    const int nt = K / BK;

    float4 pa0, pa1, pb0, pb1;
    pa0 = *reinterpret_cast<const float4*>(Ap);
    pa1 = *reinterpret_cast<const float4*>(Ap + 8);
    pb0 = *reinterpret_cast<const float4*>(Bp);
    pb1 = *reinterpret_cast<const float4*>(Bp + 64);

    {
        float* as0 = sm;
        float* bs0 = sm + AS_F;
        #pragma unroll
        for (int i = 0; i < 4; i++) {
            as0[(lk + i) * APAD + lrow]     = (&pa0.x)[i];
            as0[(lk + 8 + i) * APAD + lrow] = (&pa1.x)[i];
            float v0 = (&pb0.x)[i], v1 = (&pb1.x)[i];
            *reinterpret_cast<float2*>(&bs0[brow * BPAD + 2 * (bcol + i)])      = make_float2(v0, v0);
            *reinterpret_cast<float2*>(&bs0[brow * BPAD + 2 * (64 + bcol + i)]) = make_float2(v1, v1);
        }
    }
    __syncthreads();

    u64 acc[4][8];
    #pragma unroll
    for (int i = 0; i < 4; i++)
        #pragma unroll
        for (int j = 0; j < 8; j++) acc[i][j] = 0ULL;

    for (int t = 0; t < nt; ++t) {
        const int cur = t & 1;
        if (t + 1 < nt) {
            const long long offA = (long long)(t + 1) * BK;
            const long long offB = (long long)(t + 1) * BK * N;
            pa0 = *reinterpret_cast<const float4*>(Ap + offA);
            pa1 = *reinterpret_cast<const float4*>(Ap + offA + 8);
            pb0 = *reinterpret_cast<const float4*>(Bp + offB);
            pb1 = *reinterpret_cast<const float4*>(Bp + offB + 64);
        }

        compute_stage(sm + cur * STG_F, sm + cur * STG_F + AS_F, ty, tx, acc);

        if (t + 1 < nt) {
            float* asn = sm + (cur ^ 1) * STG_F;
            float* bsn = asn + AS_F;
            #pragma unroll
            for (int i = 0; i < 4; i++) {
                asn[(lk + i) * APAD + lrow]     = (&pa0.x)[i];
                asn[(lk + 8 + i) * APAD + lrow] = (&pa1.x)[i];
                float v0 = (&pb0.x)[i], v1 = (&pb1.x)[i];
                *reinterpret_cast<float2*>(&bsn[brow * BPAD + 2 * (bcol + i)])      = make_float2(v0, v0);
                *reinterpret_cast<float2*>(&bsn[brow * BPAD + 2 * (64 + bcol + i)]) = make_float2(v1, v1);
            }
        }
        __syncthreads();
    }

    epilogue_store(acc, C, N, m0, n0, ty, tx, nullptr, 1.f);
}

// ---------------------------------------------------------------------------
// Small kernels: transpose, MVs, softmax
// ---------------------------------------------------------------------------
__global__ void transpose1024(const float* __restrict__ src, float* __restrict__ dst)
{
    __shared__ float t[32][33];
    int x = blockIdx.x * 32 + threadIdx.x;
    int y = blockIdx.y * 32 + threadIdx.y;
    #pragma unroll
    for (int i = 0; i < 4; i++)
        t[threadIdx.y + 8 * i][threadIdx.x] = src[(y + 8 * i) * HDIM + x];
    __syncthreads();
    x = blockIdx.y * 32 + threadIdx.x;
    y = blockIdx.x * 32 + threadIdx.y;
    #pragma unroll
    for (int i = 0; i < 4; i++)
        dst[(y + 8 * i) * HDIM + x] = t[threadIdx.x][threadIdx.y + 8 * i];
}

// u[h] = sum_o Wk[o,h] * bq[o]   (coalesced across h)
__global__ void mv_u(const float* __restrict__ Wk, const float* __restrict__ bq,
                     float* __restrict__ u)
{
    int h = blockIdx.x * blockDim.x + threadIdx.x;
    float s = 0.f;
    for (int o = 0; o < HDIM; o++) s += Wk[(long long)o * HDIM + h] * bq[o];
    u[h] = s;
}

// c[i] = 0.125 * sum_h X[i,h] * u[h]   (one warp per row)
__global__ void mv_c(const float* __restrict__ X, const float* __restrict__ u,
                     float* __restrict__ c)
{
    int row = blockIdx.x * 8 + (threadIdx.x >> 5);
    int lane = threadIdx.x & 31;
    const float* xr = X + (long long)row * HDIM;
    float s = 0.f;
    for (int h = lane; h < HDIM; h += 32) s += xr[h] * u[h];
    #pragma unroll
    for (int o = 16; o > 0; o >>= 1) s += __shfl_xor_sync(0xffffffffu, s, o);
    if (lane == 0) c[row] = 0.125f * s;
}

// d[a] = sum_cc Wo[a,cc] * bv[cc] + bo[a]   (one warp per row)
__global__ void mv_d(const float* __restrict__ Wo, const float* __restrict__ bv,
                     const float* __restrict__ bo, float* __restrict__ d)
{
    int row = blockIdx.x * 8 + (threadIdx.x >> 5);
    int lane = threadIdx.x & 31;
    const float* wr = Wo + (long long)row * HDIM;
    float s = 0.f;
    for (int h = lane; h < HDIM; h += 32) s += wr[h] * bv[h];
    #pragma unroll
    for (int o = 16; o > 0; o >>= 1) s += __shfl_xor_sync(0xffffffffu, s, o);
    if (lane == 0) d[row] = s + bo[row];
}

__device__ __forceinline__ float warp_max(float v) {
    #pragma unroll
    for (int o = 16; o > 0; o >>= 1) v = fmaxf(v, __shfl_xor_sync(0xffffffffu, v, o));
    return v;
}
__device__ __forceinline__ float warp_sum(float v) {
    #pragma unroll
    for (int o = 16; o > 0; o >>= 1) v += __shfl_xor_sync(0xffffffffu, v, o);
    return v;
}

__global__ __launch_bounds__(256)
void softmax_rows(float* __restrict__ S)
{
    const int tid = threadIdx.x;
    float* r = S + (size_t)blockIdx.x * SDIM;

    __shared__ float red[8];

    float v[16];
    float mx = -1e30f;
    #pragma unroll
    for (int i = 0; i < 16; i++) {
        v[i] = r[tid + i * 256];
        mx = fmaxf(mx, v[i]);
    }
    mx = warp_max(mx);
    if ((tid & 31) == 0) red[tid >> 5] = mx;
    __syncthreads();
    {
        float t = (tid < 8) ? red[tid] : -1e30f;
        t = warp_max(t);
        if (tid == 0) red[0] = t;
    }
    __syncthreads();
    mx = red[0];
    __syncthreads();

    float sum = 0.f;
    #pragma unroll
    for (int i = 0; i < 16; i++) {
        v[i] = __expf(v[i] - mx);
        sum += v[i];
    }
    sum = warp_sum(sum);
    if ((tid & 31) == 0) red[tid >> 5] = sum;
    __syncthreads();
    {
        float t = (tid < 8) ? red[tid] : 0.f;
        t = warp_sum(t);
        if (tid == 0) red[0] = t;
    }
    __syncthreads();
    const float inv = 1.f / red[0];

    #pragma unroll
    for (int i = 0; i < 16; i++)
        r[tid + i * 256] = v[i] * inv;
}

// ---------------------------------------------------------------------------
// Launch. Algebra:
//   scores ~ (x_i^T G x_j + u.x_j)/8,   G = Wq^T Wk, u = Wk^T bq
//   (per-row-constant terms dropped: softmax invariant)
//   out = (P X) H^T + d,  H = Wo Wv, d = Wo bv + bo  (P rows sum to 1)
// ---------------------------------------------------------------------------
extern "C" void kernel_launch(void* const* d_in, const int* in_sizes, int n_in,
                              void* d_out, int out_size)
{
    const float* x  = (const float*)d_in[0];
    const float* Wq = (const float*)d_in[1];
    const float* bq = (const float*)d_in[2];
    const float* Wk = (const float*)d_in[3];
    const float* Wv = (const float*)d_in[5];
    const float* bv = (const float*)d_in[6];
    const float* Wo = (const float*)d_in[7];
    const float* bo = (const float*)d_in[8];
    float* out = (float*)d_out;

    cudaFuncSetAttribute(sgemm_nt, cudaFuncAttributeMaxDynamicSharedMemorySize, DSMEM_BYTES);
    cudaFuncSetAttribute(sgemm_nn, cudaFuncAttributeMaxDynamicSharedMemorySize, DSMEM_BYTES);

    const dim3 blk(256);
    const long long SH = (long long)SDIM * HDIM;
    const long long SS = (long long)SDIM * SDIM;

    // Precomputes
    transpose1024<<<dim3(32, 32), dim3(32, 8)>>>(Wq, g_wqt);
    sgemm_nn<<<dim3(8, 8), blk, DSMEM_BYTES>>>(g_wqt, Wk, g_G, HDIM, HDIM, HDIM, 0, 0, 0);
    sgemm_nn<<<dim3(8, 8), blk, DSMEM_BYTES>>>(Wo, Wv, g_H, HDIM, HDIM, HDIM, 0, 0, 0);
    mv_u<<<4, 256>>>(Wk, bq, g_u);
    mv_c<<<MDIM / 8, 256>>>(x, g_u, g_c);
    mv_d<<<HDIM / 8, 256>>>(Wo, bv, bo, g_d);

    // T = X * G   [8192 x 1024]
    sgemm_nn<<<dim3(8, 64), blk, DSMEM_BYTES>>>(x, g_G, g_T, MDIM, HDIM, HDIM, 0, 0, 0);

    // scores = (T * X^T)/8 + c_j   (per batch)
    sgemm_nt<<<dim3(32, 32, BDIM), blk, DSMEM_BYTES>>>(g_T, x, g_c, g_s,
        SDIM, SDIM, HDIM, 0.125f, SH, SH, SS, SDIM);

    // softmax rows (in place)
    softmax_rows<<<BDIM * SDIM, 256>>>(g_s);

    // U = P * X   (per batch)  [4096 x 1024]
    sgemm_nn<<<dim3(8, 32, BDIM), blk, DSMEM_BYTES>>>(g_s, x, g_U,
        SDIM, HDIM, SDIM, SS, SH, SH);

    // out = U * H^T + d
    sgemm_nt<<<dim3(8, 64), blk, DSMEM_BYTES>>>(g_U, g_H, g_d, out,
        MDIM, HDIM, HDIM, 1.f, 0, 0, 0, 0);
}

// round 11
// speedup vs baseline: 1.4705x; 1.0876x over previous
#include <cuda_runtime.h>
#include <math.h>
#include <stdint.h>

// Problem shape: B=2, S=4096, H=1024, M=B*S=8192
#define BDIM 2
#define SDIM 4096
#define HDIM 1024
#define MDIM 8192

#define KST 64            // K per smem stage
#define KFF 40            // k-range handled by FFMA pipe (62.5%)
#define PADX 132          // floats per smem k-row
#define SMEM_BYTES (2 * KST * PADX * 4)   // 67584

// Scratch
__device__ float g_wqt[(size_t)HDIM * HDIM];   // Wq^T
__device__ float g_G[(size_t)HDIM * HDIM];     // Wq^T * Wk
__device__ float g_H[(size_t)HDIM * HDIM];     // Wo * Wv
__device__ float g_T[(size_t)MDIM * HDIM];     // X * G
__device__ float g_U[(size_t)MDIM * HDIM];     // P * X
__device__ float g_s[(size_t)BDIM * SDIM * SDIM];
__device__ float g_c[MDIM];
__device__ float g_u[HDIM];
__device__ float g_d[HDIM];

// ---------------- helpers ----------------
__device__ __forceinline__ uint32_t tf32hi(float x) {
    uint32_t y;
    asm("cvt.rna.tf32.f32 %0, %1;" : "=r"(y) : "f"(x));
    return y;
}
__device__ __forceinline__ float u2f(uint32_t u) { return __uint_as_float(u); }

__device__ __forceinline__ void mma8(float* d, const uint32_t* a, uint32_t b0, uint32_t b1) {
    asm volatile(
        "mma.sync.aligned.m16n8k8.row.col.f32.tf32.tf32.f32 "
        "{%0,%1,%2,%3}, {%4,%5,%6,%7}, {%8,%9}, {%0,%1,%2,%3};\n"
        : "+f"(d[0]), "+f"(d[1]), "+f"(d[2]), "+f"(d[3])
        : "r"(a[0]), "r"(a[1]), "r"(a[2]), "r"(a[3]), "r"(b0), "r"(b1));
}

// ---------------------------------------------------------------------------
// FFMA part: k in [0, KFF). Accumulates into mma-fragment-layout acc.
// Warp tile 32(m) x 64(n): mt=2 (16 rows each), nt=8 (8 cols each).
// Lane (r = lane>>2, c = lane&3) owns rows {base+r, base+r+8}, cols {2c, 2c+1}.
// ---------------------------------------------------------------------------
__device__ __forceinline__ void ffma_part(
    const float* __restrict__ As, const float* __restrict__ Bs,
    int wm, int wn, int r, int c, float acc[2][8][4])
{
    #pragma unroll 4
    for (int k = 0; k < KFF; ++k) {
        const float* ar = As + k * PADX + wm + r;
        const float* br = Bs + k * PADX + wn + 2 * c;
        float a00 = ar[0],  a01 = ar[8];    // mt0: rows r, r+8
        float a10 = ar[16], a11 = ar[24];   // mt1
        #pragma unroll
        for (int nt = 0; nt < 8; nt++) {
            float2 b = *reinterpret_cast<const float2*>(br + 8 * nt);
            acc[0][nt][0] += a00 * b.x; acc[0][nt][1] += a00 * b.y;
            acc[0][nt][2] += a01 * b.x; acc[0][nt][3] += a01 * b.y;
            acc[1][nt][0] += a10 * b.x; acc[1][nt][1] += a10 * b.y;
            acc[1][nt][2] += a11 * b.x; acc[1][nt][3] += a11 * b.y;
        }
    }
}

// ---------------------------------------------------------------------------
// MMA part: k in [KFF, KST), 3 chunks of k8, tf32x3 (hh + hl + lh).
// ---------------------------------------------------------------------------
__device__ __forceinline__ void mma_part(
    const float* __restrict__ As, const float* __restrict__ Bs,
    int wm, int wn, int r, int c, float acc[2][8][4])
{
    for (int ks = 0; ks < 3; ++ks) {
        const int k = KFF + ks * 8;
        const float* a0 = As + (k + c) * PADX + wm + r;
        const float* a1 = As + (k + c + 4) * PADX + wm + r;
        uint32_t ah[2][4], al[2][4];
        #pragma unroll
        for (int mt = 0; mt < 2; mt++) {
            float s0 = a0[mt * 16], s1 = a0[mt * 16 + 8];
            float s2 = a1[mt * 16], s3 = a1[mt * 16 + 8];
            ah[mt][0] = tf32hi(s0); ah[mt][1] = tf32hi(s1);
            ah[mt][2] = tf32hi(s2); ah[mt][3] = tf32hi(s3);
            al[mt][0] = tf32hi(s0 - u2f(ah[mt][0]));
            al[mt][1] = tf32hi(s1 - u2f(ah[mt][1]));
            al[mt][2] = tf32hi(s2 - u2f(ah[mt][2]));
            al[mt][3] = tf32hi(s3 - u2f(ah[mt][3]));
        }
        const float* b0p = Bs + (k + c) * PADX + wn + r;
        const float* b1p = Bs + (k + c + 4) * PADX + wn + r;
        #pragma unroll
        for (int nt = 0; nt < 8; nt++) {
            float t0 = b0p[8 * nt], t1 = b1p[8 * nt];
            uint32_t bh0 = tf32hi(t0), bh1 = tf32hi(t1);
            uint32_t bl0 = tf32hi(t0 - u2f(bh0)), bl1 = tf32hi(t1 - u2f(bh1));
            #pragma unroll
            for (int mt = 0; mt < 2; mt++) {
                mma8(acc[mt][nt], ah[mt], bh0, bh1);  // hi*hi
                mma8(acc[mt][nt], ah[mt], bl0, bl1);  // hi*lo
                mma8(acc[mt][nt], al[mt], bh0, bh1);  // lo*hi
            }
        }
    }
}

// ---------------------------------------------------------------------------
// Hybrid dual-pipe GEMM. BT=true: B is [N,K] (NT); BT=false: B is [K,N] (NN).
// C[m,n] = alpha * sum_k A[m,k]*B'[k,n] + bias[n].  M,N % 128 == 0, K % 64 == 0.
// CTA tile 128x128, 256 threads, 8 warps (4m x 2n of 32x64 warp tiles).
// smem: As[64][132], Bs[64][132] fp32, single-buffered.
// ---------------------------------------------------------------------------
template <bool BT>
__global__ __launch_bounds__(256, 1)
void hgemm(const float* __restrict__ A, const float* __restrict__ B,
           const float* __restrict__ bias, float* __restrict__ C,
           int M, int N, int K, float alpha,
           long long sA, long long sB, long long sC, long long sBias)
{
    extern __shared__ float sm[];
    float* As = sm;
    float* Bs = sm + KST * PADX;

    A += (long long)blockIdx.z * sA;
    B += (long long)blockIdx.z * sB;
    C += (long long)blockIdx.z * sC;
    if (bias) bias += (long long)blockIdx.z * sBias;

    const int tid  = threadIdx.x;
    const int lane = tid & 31;
    const int wid  = tid >> 5;
    const int r = lane >> 2;
    const int c = lane & 3;
    const int wm = (wid & 3) * 32;
    const int wn = (wid >> 2) * 64;

    const long long m0 = (long long)blockIdx.y * 128;
    const long long n0 = (long long)blockIdx.x * 128;

    // loader mappings
    const int arow = tid >> 1;          // 0..127
    const int akb  = (tid & 1) * 32;    // 0 or 32
    const int bkr  = tid >> 2;          // 0..63   (NN B rows)
    const int bnc  = (tid & 3) * 32;    // 0..96

    float acc[2][8][4];
    #pragma unroll
    for (int i = 0; i < 2; i++)
        #pragma unroll
        for (int j = 0; j < 8; j++)
            #pragma unroll
            for (int q = 0; q < 4; q++) acc[i][j][q] = 0.f;

    for (int k0 = 0; k0 < K; k0 += KST) {
        // Stage A: transpose [m][k] -> As[k][m]
        {
            const float* Ap = A + (m0 + arow) * K + k0 + akb;
            float4 v[8];
            #pragma unroll
            for (int i = 0; i < 8; i++)
                v[i] = *reinterpret_cast<const float4*>(Ap + 4 * i);
            #pragma unroll
            for (int i = 0; i < 8; i++) {
                As[(akb + 4 * i + 0) * PADX + arow] = v[i].x;
                As[(akb + 4 * i + 1) * PADX + arow] = v[i].y;
                As[(akb + 4 * i + 2) * PADX + arow] = v[i].z;
                As[(akb + 4 * i + 3) * PADX + arow] = v[i].w;
            }
        }
        // Stage B
        if (BT) {
            const float* Bp = B + (n0 + arow) * K + k0 + akb;
            float4 v[8];
            #pragma unroll
            for (int i = 0; i < 8; i++)
                v[i] = *reinterpret_cast<const float4*>(Bp + 4 * i);
            #pragma unroll
            for (int i = 0; i < 8; i++) {
                Bs[(akb + 4 * i + 0) * PADX + arow] = v[i].x;
                Bs[(akb + 4 * i + 1) * PADX + arow] = v[i].y;
                Bs[(akb + 4 * i + 2) * PADX + arow] = v[i].z;
                Bs[(akb + 4 * i + 3) * PADX + arow] = v[i].w;
            }
        } else {
            const float* Bp = B + (long long)(k0 + bkr) * N + n0 + bnc;
            float4 v[8];
            #pragma unroll
            for (int i = 0; i < 8; i++)
                v[i] = *reinterpret_cast<const float4*>(Bp + 4 * i);
            #pragma unroll
            for (int i = 0; i < 8; i++)
                *reinterpret_cast<float4*>(&Bs[bkr * PADX + bnc + 4 * i]) = v[i];
        }
        __syncthreads();

        // dual-pipe compute; warp parity staggers pipe usage
        if (wid & 1) {
            mma_part(As, Bs, wm, wn, r, c, acc);
            ffma_part(As, Bs, wm, wn, r, c, acc);
        } else {
            ffma_part(As, Bs, wm, wn, r, c, acc);
            mma_part(As, Bs, wm, wn, r, c, acc);
        }
        __syncthreads();
    }

    // Epilogue (mma fragment layout)
    #pragma unroll
    for (int mt = 0; mt < 2; mt++) {
        long long row0 = m0 + wm + mt * 16 + r;
        #pragma unroll
        for (int nt = 0; nt < 8; nt++) {
            int col = wn + nt * 8 + 2 * c;
            float bx = 0.f, by = 0.f;
            if (bias) {
                float2 bb = *reinterpret_cast<const float2*>(bias + n0 + col);
                bx = bb.x; by = bb.y;
            }
            float2 o0 = make_float2(alpha * acc[mt][nt][0] + bx,
                                    alpha * acc[mt][nt][1] + by);
            float2 o1 = make_float2(alpha * acc[mt][nt][2] + bx,
                                    alpha * acc[mt][nt][3] + by);
            *reinterpret_cast<float2*>(C + row0 * N + n0 + col)       = o0;
            *reinterpret_cast<float2*>(C + (row0 + 8) * N + n0 + col) = o1;
        }
    }
}

// ---------------------------------------------------------------------------
// Small kernels
// ---------------------------------------------------------------------------
__global__ void transpose1024(const float* __restrict__ src, float* __restrict__ dst)
{
    __shared__ float t[32][33];
    int x = blockIdx.x * 32 + threadIdx.x;
    int y = blockIdx.y * 32 + threadIdx.y;
    #pragma unroll
    for (int i = 0; i < 4; i++)
        t[threadIdx.y + 8 * i][threadIdx.x] = src[(y + 8 * i) * HDIM + x];
    __syncthreads();
    x = blockIdx.y * 32 + threadIdx.x;
    y = blockIdx.x * 32 + threadIdx.y;
    #pragma unroll
    for (int i = 0; i < 4; i++)
        dst[(y + 8 * i) * HDIM + x] = t[threadIdx.x][threadIdx.y + 8 * i];
}

__global__ void mv_u(const float* __restrict__ Wk, const float* __restrict__ bq,
                     float* __restrict__ u)
{
    int h = blockIdx.x * blockDim.x + threadIdx.x;
    float s = 0.f;
    for (int o = 0; o < HDIM; o++) s += Wk[(long long)o * HDIM + h] * bq[o];
    u[h] = s;
}

__global__ void mv_c(const float* __restrict__ X, const float* __restrict__ u,
                     float* __restrict__ c)
{
    int row = blockIdx.x * 8 + (threadIdx.x >> 5);
    int lane = threadIdx.x & 31;
    const float* xr = X + (long long)row * HDIM;
    float s = 0.f;
    for (int h = lane; h < HDIM; h += 32) s += xr[h] * u[h];
    #pragma unroll
    for (int o = 16; o > 0; o >>= 1) s += __shfl_xor_sync(0xffffffffu, s, o);
    if (lane == 0) c[row] = 0.125f * s;
}

__global__ void mv_d(const float* __restrict__ Wo, const float* __restrict__ bv,
                     const float* __restrict__ bo, float* __restrict__ d)
{
    int row = blockIdx.x * 8 + (threadIdx.x >> 5);
    int lane = threadIdx.x & 31;
    const float* wr = Wo + (long long)row * HDIM;
    float s = 0.f;
    for (int h = lane; h < HDIM; h += 32) s += wr[h] * bv[h];
    #pragma unroll
    for (int o = 16; o > 0; o >>= 1) s += __shfl_xor_sync(0xffffffffu, s, o);
    if (lane == 0) d[row] = s + bo[row];
}

__device__ __forceinline__ float warp_max(float v) {
    #pragma unroll
    for (int o = 16; o > 0; o >>= 1) v = fmaxf(v, __shfl_xor_sync(0xffffffffu, v, o));
    return v;
}
__device__ __forceinline__ float warp_sum(float v) {
    #pragma unroll
    for (int o = 16; o > 0; o >>= 1) v += __shfl_xor_sync(0xffffffffu, v, o);
    return v;
}

__global__ __launch_bounds__(256)
void softmax_rows(float* __restrict__ S)
{
    const int tid = threadIdx.x;
    float* rp = S + (size_t)blockIdx.x * SDIM;

    __shared__ float red[8];

    float v[16];
    float mx = -1e30f;
    #pragma unroll
    for (int i = 0; i < 16; i++) {
        v[i] = rp[tid + i * 256];
        mx = fmaxf(mx, v[i]);
    }
    mx = warp_max(mx);
    if ((tid & 31) == 0) red[tid >> 5] = mx;
    __syncthreads();
    {
        float t = (tid < 8) ? red[tid] : -1e30f;
        t = warp_max(t);
        if (tid == 0) red[0] = t;
    }
    __syncthreads();
    mx = red[0];
    __syncthreads();

    float sum = 0.f;
    #pragma unroll
    for (int i = 0; i < 16; i++) {
        v[i] = __expf(v[i] - mx);
        sum += v[i];
    }
    sum = warp_sum(sum);
    if ((tid & 31) == 0) red[tid >> 5] = sum;
    __syncthreads();
    {
        float t = (tid < 8) ? red[tid] : 0.f;
        t = warp_sum(t);
        if (tid == 0) red[0] = t;
    }
    __syncthreads();
    const float inv = 1.f / red[0];

    #pragma unroll
    for (int i = 0; i < 16; i++)
        rp[tid + i * 256] = v[i] * inv;
}

// ---------------------------------------------------------------------------
// Launch. Algebra (validated round 10):
//   scores ~ (x_i^T G x_j)/8 + c_j,  G = Wq^T Wk, c = 0.125 X (Wk^T bq)
//   out = (P X) H^T + d,  H = Wo Wv, d = Wo bv + bo
// ---------------------------------------------------------------------------
extern "C" void kernel_launch(void* const* d_in, const int* in_sizes, int n_in,
                              void* d_out, int out_size)
{
    const float* x  = (const float*)d_in[0];
    const float* Wq = (const float*)d_in[1];
    const float* bq = (const float*)d_in[2];
    const float* Wk = (const float*)d_in[3];
    const float* Wv = (const float*)d_in[5];
    const float* bv = (const float*)d_in[6];
    const float* Wo = (const float*)d_in[7];
    const float* bo = (const float*)d_in[8];
    float* out = (float*)d_out;

    cudaFuncSetAttribute(hgemm<true>,  cudaFuncAttributeMaxDynamicSharedMemorySize, SMEM_BYTES);
    cudaFuncSetAttribute(hgemm<false>, cudaFuncAttributeMaxDynamicSharedMemorySize, SMEM_BYTES);

    const dim3 blk(256);
    const long long SH = (long long)SDIM * HDIM;
    const long long SS = (long long)SDIM * SDIM;

    // Precomputes
    transpose1024<<<dim3(32, 32), dim3(32, 8)>>>(Wq, g_wqt);
    hgemm<false><<<dim3(8, 8), blk, SMEM_BYTES>>>(g_wqt, Wk, nullptr, g_G,
        HDIM, HDIM, HDIM, 1.f, 0, 0, 0, 0);
    hgemm<false><<<dim3(8, 8), blk, SMEM_BYTES>>>(Wo, Wv, nullptr, g_H,
        HDIM, HDIM, HDIM, 1.f, 0, 0, 0, 0);
    mv_u<<<4, 256>>>(Wk, bq, g_u);
    mv_c<<<MDIM / 8, 256>>>(x, g_u, g_c);
    mv_d<<<HDIM / 8, 256>>>(Wo, bv, bo, g_d);

    // T = X * G   [8192 x 1024]
    hgemm<false><<<dim3(8, 64), blk, SMEM_BYTES>>>(x, g_G, nullptr, g_T,
        MDIM, HDIM, HDIM, 1.f, 0, 0, 0, 0);

    // scores = 0.125 * (T X^T) + c_j   (per batch)
    hgemm<true><<<dim3(32, 32, BDIM), blk, SMEM_BYTES>>>(g_T, x, g_c, g_s,
        SDIM, SDIM, HDIM, 0.125f, SH, SH, SS, SDIM);

    // softmax rows (in place)
    softmax_rows<<<BDIM * SDIM, 256>>>(g_s);

    // U = P * X   (per batch)
    hgemm<false><<<dim3(8, 32, BDIM), blk, SMEM_BYTES>>>(g_s, x, nullptr, g_U,
        SDIM, HDIM, SDIM, 1.f, SS, SH, SH, 0);

    // out = U * H^T + d
    hgemm<true><<<dim3(8, 64), blk, SMEM_BYTES>>>(g_U, g_H, g_d, out,
        MDIM, HDIM, HDIM, 1.f, 0, 0, 0, 0);
}

// round 12
// speedup vs baseline: 1.5034x; 1.0224x over previous
#include <cuda_runtime.h>
#include <math.h>
#include <stdint.h>

// Problem shape: B=2, S=4096, H=1024, M=B*S=8192
#define BDIM 2
#define SDIM 4096
#define HDIM 1024
#define MDIM 8192

#define KST 64            // K per smem stage
#define KFF 32            // k-range on FFMA pipe (rest on tensor pipe)
#define PADX 132          // floats per smem k-row
#define TILEF (KST * PADX)         // floats per tile (A or B)
#define STGF (2 * TILEF)           // floats per stage (A + B)
#define SMEM_BYTES (2 * STGF * 4)  // 2 stages = 135168 B

// Scratch
__device__ float g_wqt[(size_t)HDIM * HDIM];   // Wq^T
__device__ float g_G[(size_t)HDIM * HDIM];     // Wq^T * Wk
__device__ float g_H[(size_t)HDIM * HDIM];     // Wo * Wv
__device__ float g_T[(size_t)MDIM * HDIM];     // X * G
__device__ float g_U[(size_t)MDIM * HDIM];     // P * X
__device__ float g_s[(size_t)BDIM * SDIM * SDIM];
__device__ float g_c[MDIM];
__device__ float g_u[HDIM];
__device__ float g_upart[32][HDIM];
__device__ float g_d[HDIM];

// ---------------- helpers ----------------
__device__ __forceinline__ uint32_t tf32hi(float x) {
    uint32_t y;
    asm("cvt.rna.tf32.f32 %0, %1;" : "=r"(y) : "f"(x));
    return y;
}
__device__ __forceinline__ float u2f(uint32_t u) { return __uint_as_float(u); }

__device__ __forceinline__ void mma8(float* d, const uint32_t* a, uint32_t b0, uint32_t b1) {
    asm volatile(
        "mma.sync.aligned.m16n8k8.row.col.f32.tf32.tf32.f32 "
        "{%0,%1,%2,%3}, {%4,%5,%6,%7}, {%8,%9}, {%0,%1,%2,%3};\n"
        : "+f"(d[0]), "+f"(d[1]), "+f"(d[2]), "+f"(d[3])
        : "r"(a[0]), "r"(a[1]), "r"(a[2]), "r"(a[3]), "r"(b0), "r"(b1));
}

// ---------------------------------------------------------------------------
// FFMA part: k in [0, KFF). mma-fragment-layout accumulators.
// Warp tile 32(m) x 64(n). Lane (r=lane>>2, c=lane&3) owns rows {base+r, +8},
// cols {2c, 2c+1} of each 16x8 mma tile.
// ---------------------------------------------------------------------------
__device__ __forceinline__ void ffma_part(
    const float* __restrict__ As, const float* __restrict__ Bs,
    int wm, int wn, int r, int c, float acc[2][8][4])
{
    #pragma unroll 4
    for (int k = 0; k < KFF; ++k) {
        const float* ar = As + k * PADX + wm + r;
        const float* br = Bs + k * PADX + wn + 2 * c;
        float a00 = ar[0],  a01 = ar[8];
        float a10 = ar[16], a11 = ar[24];
        #pragma unroll
        for (int nt = 0; nt < 8; nt++) {
            float2 b = *reinterpret_cast<const float2*>(br + 8 * nt);
            acc[0][nt][0] += a00 * b.x; acc[0][nt][1] += a00 * b.y;
            acc[0][nt][2] += a01 * b.x; acc[0][nt][3] += a01 * b.y;
            acc[1][nt][0] += a10 * b.x; acc[1][nt][1] += a10 * b.y;
            acc[1][nt][2] += a11 * b.x; acc[1][nt][3] += a11 * b.y;
        }
    }
}

// ---------------------------------------------------------------------------
// MMA part: k in [KFF, KST), 4 chunks of k8, tf32x2 (hh + lh; hl dropped —
// B-lo conversions eliminated; accuracy headroom validated rounds 10/11).
// ---------------------------------------------------------------------------
__device__ __forceinline__ void mma_part(
    const float* __restrict__ As, const float* __restrict__ Bs,
    int wm, int wn, int r, int c, float acc[2][8][4])
{
    #pragma unroll
    for (int ks = 0; ks < (KST - KFF) / 8; ++ks) {
        const int k = KFF + ks * 8;
        const float* a0 = As + (k + c) * PADX + wm + r;
        const float* a1 = As + (k + c + 4) * PADX + wm + r;
        uint32_t ah[2][4], al[2][4];
        #pragma unroll
        for (int mt = 0; mt < 2; mt++) {
            float s0 = a0[mt * 16], s1 = a0[mt * 16 + 8];
            float s2 = a1[mt * 16], s3 = a1[mt * 16 + 8];
            ah[mt][0] = tf32hi(s0); ah[mt][1] = tf32hi(s1);
            ah[mt][2] = tf32hi(s2); ah[mt][3] = tf32hi(s3);
            al[mt][0] = tf32hi(s0 - u2f(ah[mt][0]));
            al[mt][1] = tf32hi(s1 - u2f(ah[mt][1]));
            al[mt][2] = tf32hi(s2 - u2f(ah[mt][2]));
            al[mt][3] = tf32hi(s3 - u2f(ah[mt][3]));
        }
        const float* b0p = Bs + (k + c) * PADX + wn + r;
        const float* b1p = Bs + (k + c + 4) * PADX + wn + r;
        #pragma unroll
        for (int nt = 0; nt < 8; nt++) {
            uint32_t bh0 = tf32hi(b0p[8 * nt]);
            uint32_t bh1 = tf32hi(b1p[8 * nt]);
            #pragma unroll
            for (int mt = 0; mt < 2; mt++) {
                mma8(acc[mt][nt], ah[mt], bh0, bh1);  // hi*hi
                mma8(acc[mt][nt], al[mt], bh0, bh1);  // lo*hi
            }
        }
    }
}

// ---------------------------------------------------------------------------
// Hybrid dual-pipe GEMM, register-prefetch double-buffered smem.
// BT=true: B is [N,K] (NT); BT=false: B is [K,N] (NN).
// CTA tile 128x128, 256 threads, 8 warps (4m x 2n of 32x64 warp tiles).
// ---------------------------------------------------------------------------
template <bool BT>
__global__ __launch_bounds__(256, 1)
void hgemm(const float* __restrict__ A, const float* __restrict__ B,
           const float* __restrict__ bias, float* __restrict__ C,
           int M, int N, int K, float alpha,
           long long sA, long long sB, long long sC, long long sBias)
{
    extern __shared__ float sm[];

    A += (long long)blockIdx.z * sA;
    B += (long long)blockIdx.z * sB;
    C += (long long)blockIdx.z * sC;
    if (bias) bias += (long long)blockIdx.z * sBias;

    const int tid  = threadIdx.x;
    const int lane = tid & 31;
    const int wid  = tid >> 5;
    const int r = lane >> 2;
    const int c = lane & 3;
    const int wm = (wid & 3) * 32;
    const int wn = (wid >> 2) * 64;

    const long long m0 = (long long)blockIdx.y * 128;
    const long long n0 = (long long)blockIdx.x * 128;

    // loader mappings
    const int arow = tid >> 1;          // 0..127
    const int akb  = (tid & 1) * 32;    // 0 or 32
    const int bkr  = tid >> 2;          // 0..63 (NN B rows)
    const int bnc  = (tid & 3) * 32;    // 0..96

    const float* ApA = A + (m0 + arow) * K + akb;
    const float* ApB = BT ? (B + (n0 + arow) * K + akb)
                          : (B + (long long)bkr * N + n0 + bnc);

    float acc[2][8][4];
    #pragma unroll
    for (int i = 0; i < 2; i++)
        #pragma unroll
        for (int j = 0; j < 8; j++)
            #pragma unroll
            for (int q = 0; q < 4; q++) acc[i][j][q] = 0.f;

    const int nt = K / KST;
    float4 va[8], vb[8];

    // prologue: stage 0 -> regs -> smem buffer 0
    #pragma unroll
    for (int i = 0; i < 8; i++) {
        va[i] = *reinterpret_cast<const float4*>(ApA + 4 * i);
        vb[i] = *reinterpret_cast<const float4*>(ApB + 4 * i);
    }
    {
        float* As0 = sm;
        float* Bs0 = sm + TILEF;
        #pragma unroll
        for (int i = 0; i < 8; i++) {
            As0[(akb + 4 * i + 0) * PADX + arow] = va[i].x;
            As0[(akb + 4 * i + 1) * PADX + arow] = va[i].y;
            As0[(akb + 4 * i + 2) * PADX + arow] = va[i].z;
            As0[(akb + 4 * i + 3) * PADX + arow] = va[i].w;
        }
        if (BT) {
            #pragma unroll
            for (int i = 0; i < 8; i++) {
                Bs0[(akb + 4 * i + 0) * PADX + arow] = vb[i].x;
                Bs0[(akb + 4 * i + 1) * PADX + arow] = vb[i].y;
                Bs0[(akb + 4 * i + 2) * PADX + arow] = vb[i].z;
                Bs0[(akb + 4 * i + 3) * PADX + arow] = vb[i].w;
            }
        } else {
            #pragma unroll
            for (int i = 0; i < 8; i++)
                *reinterpret_cast<float4*>(&Bs0[bkr * PADX + bnc + 4 * i]) = vb[i];
        }
    }
    __syncthreads();

    for (int t = 0; t < nt; ++t) {
        const int cur = t & 1;
        float* Asc = sm + cur * STGF;
        float* Bsc = Asc + TILEF;

        // prefetch next stage's globals into regs (overlaps with compute)
        if (t + 1 < nt) {
            const long long offA = (long long)(t + 1) * KST;
            const long long offB = BT ? offA : (long long)(t + 1) * KST * N;
            #pragma unroll
            for (int i = 0; i < 8; i++) {
                va[i] = *reinterpret_cast<const float4*>(ApA + offA + 4 * i);
                vb[i] = *reinterpret_cast<const float4*>(ApB + offB + 4 * i);
            }
        }

        // dual-pipe compute; warp parity staggers pipe usage
        if (wid & 1) {
            mma_part(Asc, Bsc, wm, wn, r, c, acc);
            ffma_part(Asc, Bsc, wm, wn, r, c, acc);
        } else {
            ffma_part(Asc, Bsc, wm, wn, r, c, acc);
            mma_part(Asc, Bsc, wm, wn, r, c, acc);
        }

        // store next stage into the other buffer (safe: last read 2 stages ago)
        if (t + 1 < nt) {
            float* Asn = sm + (cur ^ 1) * STGF;
            float* Bsn = Asn + TILEF;
            #pragma unroll
            for (int i = 0; i < 8; i++) {
                Asn[(akb + 4 * i + 0) * PADX + arow] = va[i].x;
                Asn[(akb + 4 * i + 1) * PADX + arow] = va[i].y;
                Asn[(akb + 4 * i + 2) * PADX + arow] = va[i].z;
                Asn[(akb + 4 * i + 3) * PADX + arow] = va[i].w;
            }
            if (BT) {
                #pragma unroll
                for (int i = 0; i < 8; i++) {
                    Bsn[(akb + 4 * i + 0) * PADX + arow] = vb[i].x;
                    Bsn[(akb + 4 * i + 1) * PADX + arow] = vb[i].y;
                    Bsn[(akb + 4 * i + 2) * PADX + arow] = vb[i].z;
                    Bsn[(akb + 4 * i + 3) * PADX + arow] = vb[i].w;
                }
            } else {
                #pragma unroll
                for (int i = 0; i < 8; i++)
                    *reinterpret_cast<float4*>(&Bsn[bkr * PADX + bnc + 4 * i]) = vb[i];
            }
        }
        __syncthreads();
    }

    // Epilogue (mma fragment layout)
    #pragma unroll
    for (int mt = 0; mt < 2; mt++) {
        long long row0 = m0 + wm + mt * 16 + r;
        #pragma unroll
        for (int nt2 = 0; nt2 < 8; nt2++) {
            int col = wn + nt2 * 8 + 2 * c;
            float bx = 0.f, by = 0.f;
            if (bias) {
                float2 bb = *reinterpret_cast<const float2*>(bias + n0 + col);
                bx = bb.x; by = bb.y;
            }
            float2 o0 = make_float2(alpha * acc[mt][nt2][0] + bx,
                                    alpha * acc[mt][nt2][1] + by);
            float2 o1 = make_float2(alpha * acc[mt][nt2][2] + bx,
                                    alpha * acc[mt][nt2][3] + by);
            *reinterpret_cast<float2*>(C + row0 * N + n0 + col)       = o0;
            *reinterpret_cast<float2*>(C + (row0 + 8) * N + n0 + col) = o1;
        }
    }
}

// ---------------------------------------------------------------------------
// Small kernels
// ---------------------------------------------------------------------------
__global__ void transpose1024(const float* __restrict__ src, float* __restrict__ dst)
{
    __shared__ float t[32][33];
    int x = blockIdx.x * 32 + threadIdx.x;
    int y = blockIdx.y * 32 + threadIdx.y;
    #pragma unroll
    for (int i = 0; i < 4; i++)
        t[threadIdx.y + 8 * i][threadIdx.x] = src[(y + 8 * i) * HDIM + x];
    __syncthreads();
    x = blockIdx.y * 32 + threadIdx.x;
    y = blockIdx.x * 32 + threadIdx.y;
    #pragma unroll
    for (int i = 0; i < 4; i++)
        dst[(y + 8 * i) * HDIM + x] = t[threadIdx.x][threadIdx.y + 8 * i];
}

// u = Wk^T bq, two-phase (deterministic, high MLP)
__global__ void mv_u1(const float* __restrict__ Wk, const float* __restrict__ bq)
{
    int h  = (blockIdx.x & 3) * 256 + threadIdx.x;
    int oc = (blockIdx.x >> 2) * 32;
    float s = 0.f;
    #pragma unroll 8
    for (int i = 0; i < 32; i++)
        s += Wk[(long long)(oc + i) * HDIM + h] * bq[oc + i];
    g_upart[blockIdx.x >> 2][h] = s;
}
__global__ void mv_u2()
{
    int h = blockIdx.x * 256 + threadIdx.x;
    float s = 0.f;
    #pragma unroll
    for (int i = 0; i < 32; i++) s += g_upart[i][h];
    g_u[h] = s;
}

__global__ void mv_c(const float* __restrict__ X, const float* __restrict__ u,
                     float* __restrict__ c)
{
    int row = blockIdx.x * 8 + (threadIdx.x >> 5);
    int lane = threadIdx.x & 31;
    const float* xr = X + (long long)row * HDIM;
    float s = 0.f;
    for (int h = lane; h < HDIM; h += 32) s += xr[h] * u[h];
    #pragma unroll
    for (int o = 16; o > 0; o >>= 1) s += __shfl_xor_sync(0xffffffffu, s, o);
    if (lane == 0) c[row] = 0.125f * s;
}

__global__ void mv_d(const float* __restrict__ Wo, const float* __restrict__ bv,
                     const float* __restrict__ bo, float* __restrict__ d)
{
    int row = blockIdx.x * 8 + (threadIdx.x >> 5);
    int lane = threadIdx.x & 31;
    const float* wr = Wo + (long long)row * HDIM;
    float s = 0.f;
    for (int h = lane; h < HDIM; h += 32) s += wr[h] * bv[h];
    #pragma unroll
    for (int o = 16; o > 0; o >>= 1) s += __shfl_xor_sync(0xffffffffu, s, o);
    if (lane == 0) d[row] = s + bo[row];
}

__device__ __forceinline__ float warp_max(float v) {
    #pragma unroll
    for (int o = 16; o > 0; o >>= 1) v = fmaxf(v, __shfl_xor_sync(0xffffffffu, v, o));
    return v;
}
__device__ __forceinline__ float warp_sum(float v) {
    #pragma unroll
    for (int o = 16; o > 0; o >>= 1) v += __shfl_xor_sync(0xffffffffu, v, o);
    return v;
}

__global__ __launch_bounds__(256)
void softmax_rows(float* __restrict__ S)
{
    const int tid = threadIdx.x;
    float* rp = S + (size_t)blockIdx.x * SDIM;

    __shared__ float red[8];

    float v[16];
    float mx = -1e30f;
    #pragma unroll
    for (int i = 0; i < 16; i++) {
        v[i] = rp[tid + i * 256];
        mx = fmaxf(mx, v[i]);
    }
    mx = warp_max(mx);
    if ((tid & 31) == 0) red[tid >> 5] = mx;
    __syncthreads();
    {
        float t = (tid < 8) ? red[tid] : -1e30f;
        t = warp_max(t);
        if (tid == 0) red[0] = t;
    }
    __syncthreads();
    mx = red[0];
    __syncthreads();

    float sum = 0.f;
    #pragma unroll
    for (int i = 0; i < 16; i++) {
        v[i] = __expf(v[i] - mx);
        sum += v[i];
    }
    sum = warp_sum(sum);
    if ((tid & 31) == 0) red[tid >> 5] = sum;
    __syncthreads();
    {
        float t = (tid < 8) ? red[tid] : 0.f;
        t = warp_sum(t);
        if (tid == 0) red[0] = t;
    }
    __syncthreads();
    const float inv = 1.f / red[0];

    #pragma unroll
    for (int i = 0; i < 16; i++)
        rp[tid + i * 256] = v[i] * inv;
}

// ---------------------------------------------------------------------------
// Launch. Algebra (validated rounds 10/11):
//   scores ~ (x_i^T G x_j)/8 + c_j,  G = Wq^T Wk, c = 0.125 X (Wk^T bq)
//   out = (P X) H^T + d,  H = Wo Wv, d = Wo bv + bo
// ---------------------------------------------------------------------------
extern "C" void kernel_launch(void* const* d_in, const int* in_sizes, int n_in,
                              void* d_out, int out_size)
{
    const float* x  = (const float*)d_in[0];
    const float* Wq = (const float*)d_in[1];
    const float* bq = (const float*)d_in[2];
    const float* Wk = (const float*)d_in[3];
    const float* Wv = (const float*)d_in[5];
    const float* bv = (const float*)d_in[6];
    const float* Wo = (const float*)d_in[7];
    const float* bo = (const float*)d_in[8];
    float* out = (float*)d_out;

    cudaFuncSetAttribute(hgemm<true>,  cudaFuncAttributeMaxDynamicSharedMemorySize, SMEM_BYTES);
    cudaFuncSetAttribute(hgemm<false>, cudaFuncAttributeMaxDynamicSharedMemorySize, SMEM_BYTES);

    const dim3 blk(256);
    const long long SH = (long long)SDIM * HDIM;
    const long long SS = (long long)SDIM * SDIM;

    // Precomputes
    transpose1024<<<dim3(32, 32), dim3(32, 8)>>>(Wq, g_wqt);
    hgemm<false><<<dim3(8, 8), blk, SMEM_BYTES>>>(g_wqt, Wk, nullptr, g_G,
        HDIM, HDIM, HDIM, 1.f, 0, 0, 0, 0);
    hgemm<false><<<dim3(8, 8), blk, SMEM_BYTES>>>(Wo, Wv, nullptr, g_H,
        HDIM, HDIM, HDIM, 1.f, 0, 0, 0, 0);
    mv_u1<<<128, 256>>>(Wk, bq);
    mv_u2<<<4, 256>>>();
    mv_c<<<MDIM / 8, 256>>>(x, g_u, g_c);
    mv_d<<<HDIM / 8, 256>>>(Wo, bv, bo, g_d);

    // T = X * G   [8192 x 1024]
    hgemm<false><<<dim3(8, 64), blk, SMEM_BYTES>>>(x, g_G, nullptr, g_T,
        MDIM, HDIM, HDIM, 1.f, 0, 0, 0, 0);

    // scores = 0.125 * (T X^T) + c_j   (per batch)
    hgemm<true><<<dim3(32, 32, BDIM), blk, SMEM_BYTES>>>(g_T, x, g_c, g_s,
        SDIM, SDIM, HDIM, 0.125f, SH, SH, SS, SDIM);

    // softmax rows (in place)
    softmax_rows<<<BDIM * SDIM, 256>>>(g_s);

    // U = P * X   (per batch)
    hgemm<false><<<dim3(8, 32, BDIM), blk, SMEM_BYTES>>>(g_s, x, nullptr, g_U,
        SDIM, HDIM, SDIM, 1.f, SS, SH, SH, 0);

    // out = U * H^T + d
    hgemm<true><<<dim3(8, 64), blk, SMEM_BYTES>>>(g_U, g_H, g_d, out,
        MDIM, HDIM, HDIM, 1.f, 0, 0, 0, 0);
}

// round 13
// speedup vs baseline: 1.5102x; 1.0046x over previous
#include <cuda_runtime.h>
#include <math.h>
#include <stdint.h>

// Problem shape: B=2, S=4096, H=1024, M=B*S=8192
#define BDIM 2
#define SDIM 4096
#define HDIM 1024
#define MDIM 8192

#define KST 64            // K per smem stage
#define KFF 40            // k-range on FFMA pipe (62.5%; matches 8.6:5.3 TF/s)
#define PADX 132          // floats per smem k-row
#define TILEF (KST * PADX)         // floats per tile (A or B)
#define STGF (2 * TILEF)           // floats per stage (A + B)
#define SMEM_BYTES (2 * STGF * 4)  // 2 stages = 135168 B

// Scratch
__device__ float g_wqt[(size_t)HDIM * HDIM];   // Wq^T
__device__ float g_G[(size_t)HDIM * HDIM];     // Wq^T * Wk
__device__ float g_H[(size_t)HDIM * HDIM];     // Wo * Wv
__device__ float g_T[(size_t)MDIM * HDIM];     // X * G
__device__ float g_U[(size_t)MDIM * HDIM];     // P * X
__device__ float g_s[(size_t)BDIM * SDIM * SDIM];
__device__ float g_c[MDIM];
__device__ float g_u[HDIM];
__device__ float g_upart[32][HDIM];
__device__ float g_d[HDIM];

// ---------------- helpers ----------------
__device__ __forceinline__ uint32_t tf32hi(float x) {
    uint32_t y;
    asm("cvt.rna.tf32.f32 %0, %1;" : "=r"(y) : "f"(x));
    return y;
}
__device__ __forceinline__ float u2f(uint32_t u) { return __uint_as_float(u); }

__device__ __forceinline__ void mma8(float* d, const uint32_t* a, uint32_t b0, uint32_t b1) {
    asm volatile(
        "mma.sync.aligned.m16n8k8.row.col.f32.tf32.tf32.f32 "
        "{%0,%1,%2,%3}, {%4,%5,%6,%7}, {%8,%9}, {%0,%1,%2,%3};\n"
        : "+f"(d[0]), "+f"(d[1]), "+f"(d[2]), "+f"(d[3])
        : "r"(a[0]), "r"(a[1]), "r"(a[2]), "r"(a[3]), "r"(b0), "r"(b1));
}

// ---------------------------------------------------------------------------
// FFMA part: k in [0, KFF). mma-fragment-layout accumulators.
// Warp tile 32(m) x 64(n). Lane (r=lane>>2, c=lane&3) owns rows {base+r, +8},
// cols {2c, 2c+1} of each 16x8 mma tile.
// ---------------------------------------------------------------------------
__device__ __forceinline__ void ffma_part(
    const float* __restrict__ As, const float* __restrict__ Bs,
    int wm, int wn, int r, int c, float acc[2][8][4])
{
    #pragma unroll 4
    for (int k = 0; k < KFF; ++k) {
        const float* ar = As + k * PADX + wm + r;
        const float* br = Bs + k * PADX + wn + 2 * c;
        float a00 = ar[0],  a01 = ar[8];
        float a10 = ar[16], a11 = ar[24];
        #pragma unroll
        for (int nt = 0; nt < 8; nt++) {
            float2 b = *reinterpret_cast<const float2*>(br + 8 * nt);
            acc[0][nt][0] += a00 * b.x; acc[0][nt][1] += a00 * b.y;
            acc[0][nt][2] += a01 * b.x; acc[0][nt][3] += a01 * b.y;
            acc[1][nt][0] += a10 * b.x; acc[1][nt][1] += a10 * b.y;
            acc[1][nt][2] += a11 * b.x; acc[1][nt][3] += a11 * b.y;
        }
    }
}

// ---------------------------------------------------------------------------
// MMA part: k in [KFF, KST), 3 chunks of k8, tf32x3 (hh + hl + lh).
// Full 3-term split: accuracy anchor 2e-5 (validated round 11).
// ---------------------------------------------------------------------------
__device__ __forceinline__ void mma_part(
    const float* __restrict__ As, const float* __restrict__ Bs,
    int wm, int wn, int r, int c, float acc[2][8][4])
{
    #pragma unroll
    for (int ks = 0; ks < (KST - KFF) / 8; ++ks) {
        const int k = KFF + ks * 8;
        const float* a0 = As + (k + c) * PADX + wm + r;
        const float* a1 = As + (k + c + 4) * PADX + wm + r;
        uint32_t ah[2][4], al[2][4];
        #pragma unroll
        for (int mt = 0; mt < 2; mt++) {
            float s0 = a0[mt * 16], s1 = a0[mt * 16 + 8];
            float s2 = a1[mt * 16], s3 = a1[mt * 16 + 8];
            ah[mt][0] = tf32hi(s0); ah[mt][1] = tf32hi(s1);
            ah[mt][2] = tf32hi(s2); ah[mt][3] = tf32hi(s3);
            al[mt][0] = tf32hi(s0 - u2f(ah[mt][0]));
            al[mt][1] = tf32hi(s1 - u2f(ah[mt][1]));
            al[mt][2] = tf32hi(s2 - u2f(ah[mt][2]));
            al[mt][3] = tf32hi(s3 - u2f(ah[mt][3]));
        }
        const float* b0p = Bs + (k + c) * PADX + wn + r;
        const float* b1p = Bs + (k + c + 4) * PADX + wn + r;
        #pragma unroll
        for (int nt = 0; nt < 8; nt++) {
            float t0 = b0p[8 * nt], t1 = b1p[8 * nt];
            uint32_t bh0 = tf32hi(t0), bh1 = tf32hi(t1);
            uint32_t bl0 = tf32hi(t0 - u2f(bh0)), bl1 = tf32hi(t1 - u2f(bh1));
            #pragma unroll
            for (int mt = 0; mt < 2; mt++) {
                mma8(acc[mt][nt], ah[mt], bh0, bh1);  // hi*hi
                mma8(acc[mt][nt], ah[mt], bl0, bl1);  // hi*lo
                mma8(acc[mt][nt], al[mt], bh0, bh1);  // lo*hi
            }
        }
    }
}

// ---------------------------------------------------------------------------
// Hybrid dual-pipe GEMM, register-prefetch double-buffered smem.
// BT=true: B is [N,K] (NT); BT=false: B is [K,N] (NN).
// CTA tile 128x128, 256 threads, 8 warps (4m x 2n of 32x64 warp tiles).
// Pipe stagger by (wid & 4): each SMSP (wid%4) holds one warp from {0-3} and
// one from {4-7}, so one ffma-phase and one mma-phase warp coexist per SMSP.
// ---------------------------------------------------------------------------
template <bool BT>
__global__ __launch_bounds__(256, 1)
void hgemm(const float* __restrict__ A, const float* __restrict__ B,
           const float* __restrict__ bias, float* __restrict__ C,
           int M, int N, int K, float alpha,
           long long sA, long long sB, long long sC, long long sBias)
{
    extern __shared__ float sm[];

    A += (long long)blockIdx.z * sA;
    B += (long long)blockIdx.z * sB;
    C += (long long)blockIdx.z * sC;
    if (bias) bias += (long long)blockIdx.z * sBias;

    const int tid  = threadIdx.x;
    const int lane = tid & 31;
    const int wid  = tid >> 5;
    const int r = lane >> 2;
    const int c = lane & 3;
    const int wm = (wid & 3) * 32;
    const int wn = (wid >> 2) * 64;

    const long long m0 = (long long)blockIdx.y * 128;
    const long long n0 = (long long)blockIdx.x * 128;

    // loader mappings
    const int arow = tid >> 1;          // 0..127
    const int akb  = (tid & 1) * 32;    // 0 or 32
    const int bkr  = tid >> 2;          // 0..63 (NN B rows)
    const int bnc  = (tid & 3) * 32;    // 0..96

    const float* ApA = A + (m0 + arow) * K + akb;
    const float* ApB = BT ? (B + (n0 + arow) * K + akb)
                          : (B + (long long)bkr * N + n0 + bnc);

    float acc[2][8][4];
    #pragma unroll
    for (int i = 0; i < 2; i++)
        #pragma unroll
        for (int j = 0; j < 8; j++)
            #pragma unroll
            for (int q = 0; q < 4; q++) acc[i][j][q] = 0.f;

    const int nt = K / KST;
    float4 va[8], vb[8];

    // prologue: stage 0 -> regs -> smem buffer 0
    #pragma unroll
    for (int i = 0; i < 8; i++) {
        va[i] = *reinterpret_cast<const float4*>(ApA + 4 * i);
        vb[i] = *reinterpret_cast<const float4*>(ApB + 4 * i);
    }
    {
        float* As0 = sm;
        float* Bs0 = sm + TILEF;
        #pragma unroll
        for (int i = 0; i < 8; i++) {
            As0[(akb + 4 * i + 0) * PADX + arow] = va[i].x;
            As0[(akb + 4 * i + 1) * PADX + arow] = va[i].y;
            As0[(akb + 4 * i + 2) * PADX + arow] = va[i].z;
            As0[(akb + 4 * i + 3) * PADX + arow] = va[i].w;
        }
        if (BT) {
            #pragma unroll
            for (int i = 0; i < 8; i++) {
                Bs0[(akb + 4 * i + 0) * PADX + arow] = vb[i].x;
                Bs0[(akb + 4 * i + 1) * PADX + arow] = vb[i].y;
                Bs0[(akb + 4 * i + 2) * PADX + arow] = vb[i].z;
                Bs0[(akb + 4 * i + 3) * PADX + arow] = vb[i].w;
            }
        } else {
            #pragma unroll
            for (int i = 0; i < 8; i++)
                *reinterpret_cast<float4*>(&Bs0[bkr * PADX + bnc + 4 * i]) = vb[i];
        }
    }
    __syncthreads();

    for (int t = 0; t < nt; ++t) {
        const int cur = t & 1;
        float* Asc = sm + cur * STGF;
        float* Bsc = Asc + TILEF;

        // prefetch next stage's globals into regs (overlaps with compute)
        if (t + 1 < nt) {
            const long long offA = (long long)(t + 1) * KST;
            const long long offB = BT ? offA : (long long)(t + 1) * KST * N;
            #pragma unroll
            for (int i = 0; i < 8; i++) {
                va[i] = *reinterpret_cast<const float4*>(ApA + offA + 4 * i);
                vb[i] = *reinterpret_cast<const float4*>(ApB + offB + 4 * i);
            }
        }

        // dual-pipe compute; per-SMSP stagger: warps 0-3 vs 4-7
        if (wid & 4) {
            mma_part(Asc, Bsc, wm, wn, r, c, acc);
            ffma_part(Asc, Bsc, wm, wn, r, c, acc);
        } else {
            ffma_part(Asc, Bsc, wm, wn, r, c, acc);
            mma_part(Asc, Bsc, wm, wn, r, c, acc);
        }

        // store next stage into the other buffer
        if (t + 1 < nt) {
            float* Asn = sm + (cur ^ 1) * STGF;
            float* Bsn = Asn + TILEF;
            #pragma unroll
            for (int i = 0; i < 8; i++) {
                Asn[(akb + 4 * i + 0) * PADX + arow] = va[i].x;
                Asn[(akb + 4 * i + 1) * PADX + arow] = va[i].y;
                Asn[(akb + 4 * i + 2) * PADX + arow] = va[i].z;
                Asn[(akb + 4 * i + 3) * PADX + arow] = va[i].w;
            }
            if (BT) {
                #pragma unroll
                for (int i = 0; i < 8; i++) {
                    Bsn[(akb + 4 * i + 0) * PADX + arow] = vb[i].x;
                    Bsn[(akb + 4 * i + 1) * PADX + arow] = vb[i].y;
                    Bsn[(akb + 4 * i + 2) * PADX + arow] = vb[i].z;
                    Bsn[(akb + 4 * i + 3) * PADX + arow] = vb[i].w;
                }
            } else {
                #pragma unroll
                for (int i = 0; i < 8; i++)
                    *reinterpret_cast<float4*>(&Bsn[bkr * PADX + bnc + 4 * i]) = vb[i];
            }
        }
        __syncthreads();
    }

    // Epilogue (mma fragment layout)
    #pragma unroll
    for (int mt = 0; mt < 2; mt++) {
        long long row0 = m0 + wm + mt * 16 + r;
        #pragma unroll
        for (int nt2 = 0; nt2 < 8; nt2++) {
            int col = wn + nt2 * 8 + 2 * c;
            float bx = 0.f, by = 0.f;
            if (bias) {
                float2 bb = *reinterpret_cast<const float2*>(bias + n0 + col);
                bx = bb.x; by = bb.y;
            }
            float2 o0 = make_float2(alpha * acc[mt][nt2][0] + bx,
                                    alpha * acc[mt][nt2][1] + by);
            float2 o1 = make_float2(alpha * acc[mt][nt2][2] + bx,
                                    alpha * acc[mt][nt2][3] + by);
            *reinterpret_cast<float2*>(C + row0 * N + n0 + col)       = o0;
            *reinterpret_cast<float2*>(C + (row0 + 8) * N + n0 + col) = o1;
        }
    }
}

// ---------------------------------------------------------------------------
// Small kernels
// ---------------------------------------------------------------------------
__global__ void transpose1024(const float* __restrict__ src, float* __restrict__ dst)
{
    __shared__ float t[32][33];
    int x = blockIdx.x * 32 + threadIdx.x;
    int y = blockIdx.y * 32 + threadIdx.y;
    #pragma unroll
    for (int i = 0; i < 4; i++)
        t[threadIdx.y + 8 * i][threadIdx.x] = src[(y + 8 * i) * HDIM + x];
    __syncthreads();
    x = blockIdx.y * 32 + threadIdx.x;
    y = blockIdx.x * 32 + threadIdx.y;
    #pragma unroll
    for (int i = 0; i < 4; i++)
        dst[(y + 8 * i) * HDIM + x] = t[threadIdx.x][threadIdx.y + 8 * i];
}

// u = Wk^T bq, two-phase (deterministic, high MLP)
__global__ void mv_u1(const float* __restrict__ Wk, const float* __restrict__ bq)
{
    int h  = (blockIdx.x & 3) * 256 + threadIdx.x;
    int oc = (blockIdx.x >> 2) * 32;
    float s = 0.f;
    #pragma unroll 8
    for (int i = 0; i < 32; i++)
        s += Wk[(long long)(oc + i) * HDIM + h] * bq[oc + i];
    g_upart[blockIdx.x >> 2][h] = s;
}
__global__ void mv_u2()
{
    int h = blockIdx.x * 256 + threadIdx.x;
    float s = 0.f;
    #pragma unroll
    for (int i = 0; i < 32; i++) s += g_upart[i][h];
    g_u[h] = s;
}

__global__ void mv_c(const float* __restrict__ X, const float* __restrict__ u,
                     float* __restrict__ c)
{
    int row = blockIdx.x * 8 + (threadIdx.x >> 5);
    int lane = threadIdx.x & 31;
    const float* xr = X + (long long)row * HDIM;
    float s = 0.f;
    for (int h = lane; h < HDIM; h += 32) s += xr[h] * u[h];
    #pragma unroll
    for (int o = 16; o > 0; o >>= 1) s += __shfl_xor_sync(0xffffffffu, s, o);
    if (lane == 0) c[row] = 0.125f * s;
}

__global__ void mv_d(const float* __restrict__ Wo, const float* __restrict__ bv,
                     const float* __restrict__ bo, float* __restrict__ d)
{
    int row = blockIdx.x * 8 + (threadIdx.x >> 5);
    int lane = threadIdx.x & 31;
    const float* wr = Wo + (long long)row * HDIM;
    float s = 0.f;
    for (int h = lane; h < HDIM; h += 32) s += wr[h] * bv[h];
    #pragma unroll
    for (int o = 16; o > 0; o >>= 1) s += __shfl_xor_sync(0xffffffffu, s, o);
    if (lane == 0) d[row] = s + bo[row];
}

__device__ __forceinline__ float warp_max(float v) {
    #pragma unroll
    for (int o = 16; o > 0; o >>= 1) v = fmaxf(v, __shfl_xor_sync(0xffffffffu, v, o));
    return v;
}
__device__ __forceinline__ float warp_sum(float v) {
    #pragma unroll
    for (int o = 16; o > 0; o >>= 1) v += __shfl_xor_sync(0xffffffffu, v, o);
    return v;
}

__global__ __launch_bounds__(256)
void softmax_rows(float* __restrict__ S)
{
    const int tid = threadIdx.x;
    float* rp = S + (size_t)blockIdx.x * SDIM;

    __shared__ float red[8];

    float v[16];
    float mx = -1e30f;
    #pragma unroll
    for (int i = 0; i < 16; i++) {
        v[i] = rp[tid + i * 256];
        mx = fmaxf(mx, v[i]);
    }
    mx = warp_max(mx);
    if ((tid & 31) == 0) red[tid >> 5] = mx;
    __syncthreads();
    {
        float t = (tid < 8) ? red[tid] : -1e30f;
        t = warp_max(t);
        if (tid == 0) red[0] = t;
    }
    __syncthreads();
    mx = red[0];
    __syncthreads();

    float sum = 0.f;
    #pragma unroll
    for (int i = 0; i < 16; i++) {
        v[i] = __expf(v[i] - mx);
        sum += v[i];
    }
    sum = warp_sum(sum);
    if ((tid & 31) == 0) red[tid >> 5] = sum;
    __syncthreads();
    {
        float t = (tid < 8) ? red[tid] : 0.f;
        t = warp_sum(t);
        if (tid == 0) red[0] = t;
    }
    __syncthreads();
    const float inv = 1.f / red[0];

    #pragma unroll
    for (int i = 0; i < 16; i++)
        rp[tid + i * 256] = v[i] * inv;
}

// ---------------------------------------------------------------------------
// Launch. Algebra (validated rounds 10-12):
//   scores ~ (x_i^T G x_j)/8 + c_j,  G = Wq^T Wk, c = 0.125 X (Wk^T bq)
//   out = (P X) H^T + d,  H = Wo Wv, d = Wo bv + bo
// ---------------------------------------------------------------------------
extern "C" void kernel_launch(void* const* d_in, const int* in_sizes, int n_in,
                              void* d_out, int out_size)
{
    const float* x  = (const float*)d_in[0];
    const float* Wq = (const float*)d_in[1];
    const float* bq = (const float*)d_in[2];
    const float* Wk = (const float*)d_in[3];
    const float* Wv = (const float*)d_in[5];
    const float* bv = (const float*)d_in[6];
    const float* Wo = (const float*)d_in[7];
    const float* bo = (const float*)d_in[8];
    float* out = (float*)d_out;

    cudaFuncSetAttribute(hgemm<true>,  cudaFuncAttributeMaxDynamicSharedMemorySize, SMEM_BYTES);
    cudaFuncSetAttribute(hgemm<false>, cudaFuncAttributeMaxDynamicSharedMemorySize, SMEM_BYTES);

    const dim3 blk(256);
    const long long SH = (long long)SDIM * HDIM;
    const long long SS = (long long)SDIM * SDIM;

    // Precomputes
    transpose1024<<<dim3(32, 32), dim3(32, 8)>>>(Wq, g_wqt);
    hgemm<false><<<dim3(8, 8), blk, SMEM_BYTES>>>(g_wqt, Wk, nullptr, g_G,
        HDIM, HDIM, HDIM, 1.f, 0, 0, 0, 0);
    hgemm<false><<<dim3(8, 8), blk, SMEM_BYTES>>>(Wo, Wv, nullptr, g_H,
        HDIM, HDIM, HDIM, 1.f, 0, 0, 0, 0);
    mv_u1<<<128, 256>>>(Wk, bq);
    mv_u2<<<4, 256>>>();
    mv_c<<<MDIM / 8, 256>>>(x, g_u, g_c);
    mv_d<<<HDIM / 8, 256>>>(Wo, bv, bo, g_d);

    // T = X * G   [8192 x 1024]
    hgemm<false><<<dim3(8, 64), blk, SMEM_BYTES>>>(x, g_G, nullptr, g_T,
        MDIM, HDIM, HDIM, 1.f, 0, 0, 0, 0);

    // scores = 0.125 * (T X^T) + c_j   (per batch)
    hgemm<true><<<dim3(32, 32, BDIM), blk, SMEM_BYTES>>>(g_T, x, g_c, g_s,
        SDIM, SDIM, HDIM, 0.125f, SH, SH, SS, SDIM);

    // softmax rows (in place)
    softmax_rows<<<BDIM * SDIM, 256>>>(g_s);

    // U = P * X   (per batch)
    hgemm<false><<<dim3(8, 32, BDIM), blk, SMEM_BYTES>>>(g_s, x, nullptr, g_U,
        SDIM, HDIM, SDIM, 1.f, SS, SH, SH, 0);

    // out = U * H^T + d
    hgemm<true><<<dim3(8, 64), blk, SMEM_BYTES>>>(g_U, g_H, g_d, out,
        MDIM, HDIM, HDIM, 1.f, 0, 0, 0, 0);
}